// round 6
// baseline (speedup 1.0000x reference)
#include <cuda_runtime.h>
#include <cstdint>

// GAE reverse scan: 2-way truncated-halo split + cp.async SMEM pipeline,
// 1-warp blocks for wave balance.
// R5 (NCOL=64): 512 blocks -> 3.46/SM -> 4-vs-3 block imbalance ~16% tail,
// DRAM capped at 75%. NCOL=32 -> 1024 blocks -> 6.92/SM (1.2% tail), and
// single-warp blocks replace BAR.SYNC with free __syncwarp.
//
// Chunks: y=0 scans [0,640) writes [0,384) (halo 256, coef^256~3e-5);
//         y=1 scans [384,1024) writes all. Both: 640 steps = 40 stages.
// Halo re-reads hit L2 (measured R5): DRAM traffic ~201MB (the floor).

#define T_DIM    1024
#define B_DIM    16384
#define GAMMA    0.99f
#define COEF     (0.99f * 0.97f)
#define UNR      16          // time rows per stage
#define NCOL     32          // columns per block (= blockDim.x, one warp)
#define DEPTH    6           // ring stages (24KB static smem)
#define NSTAGES  40          // 640 / UNR
#define M_SPLIT  384
#define SCAN_LEN 640

__device__ __forceinline__ uint32_t smem_u32(const void* p) {
    return (uint32_t)__cvta_generic_to_shared(p);
}

// Fill stage k_: UNR x NCOL tile of v and r via 16B cp.async.
// Tile = 512 floats per array; thread covers 4 float4 each (rows tid/8 + 4j).
#define FILL_STAGE(k_)                                                        \
    {                                                                         \
        const int ts_   = t_hi - UNR * ((k_) + 1);                            \
        const int slot_ = (k_) % DEPTH;                                       \
        const uint32_t svb = smem_u32(&sv[slot_][0]);                         \
        const uint32_t srb = smem_u32(&sr[slot_][0]);                         \
        _Pragma("unroll")                                                     \
        for (int j = 0; j < 4; j++) {                                         \
            const int flat = j * 128 + tid * 4;   /* float index in tile */   \
            const size_t g = (size_t)(ts_ + (flat >> 5)) * B_DIM              \
                           + cb + (flat & 31);                                \
            asm volatile("cp.async.cg.shared.global [%0], [%1], 16;"          \
                         :: "r"(svb + flat * 4), "l"(value + g));             \
            asm volatile("cp.async.cg.shared.global [%0], [%1], 16;"          \
                         :: "r"(srb + flat * 4), "l"(reward + g));            \
        }                                                                     \
    }

__global__ void __launch_bounds__(NCOL) gae_kernel(
    const float* __restrict__ value,   // (T+1, B)
    const float* __restrict__ reward,  // (T, B)
    float* __restrict__ adv)           // (T, B)
{
    __shared__ float sv[DEPTH][UNR * NCOL];
    __shared__ float sr[DEPTH][UNR * NCOL];

    const int tid = threadIdx.x;
    const int cb  = blockIdx.x * NCOL;
    const int b   = cb + tid;
    const bool top = (blockIdx.y != 0);

    const int t_hi = top ? T_DIM : SCAN_LEN;   // scan top (exclusive)
    const int wlim = top ? T_DIM : M_SPLIT;    // write rows with t < wlim

    float carry  = 0.0f;                       // exact (top) / truncated ~3e-5
    float v_next = value[(size_t)t_hi * B_DIM + b];

    // Prologue: DEPTH-1 stages in flight before any compute.
    #pragma unroll
    for (int s = 0; s < DEPTH - 1; s++) {
        FILL_STAGE(s);
        asm volatile("cp.async.commit_group;");
    }

    for (int k = 0; k < NSTAGES; k++) {
        // Stage k complete when <= DEPTH-2 groups pending.
        asm volatile("cp.async.wait_group %0;" :: "n"(DEPTH - 2));
        __syncwarp();   // single-warp block: cross-lane smem visibility only

        // Refill the slot freed by stage k-1 (readers done before syncwarp).
        if (k + DEPTH - 1 < NSTAGES) {
            FILL_STAGE(k + DEPTH - 1);
        }
        asm volatile("cp.async.commit_group;");   // empty tail groups keep counts aligned

        // Consume stage k: time descending within the stage.
        const int  slot     = k % DEPTH;
        const int  ts       = t_hi - UNR * (k + 1);
        const bool do_write = (ts + UNR <= wlim);
        #pragma unroll
        for (int j = UNR - 1; j >= 0; j--) {
            const float vt = sv[slot][j * NCOL + tid];
            const float rt = sr[slot][j * NCOL + tid];
            const float delta = fmaf(GAMMA, v_next, rt) - vt;
            carry = fmaf(COEF, carry, delta);
            if (do_write)
                adv[(size_t)(ts + j) * B_DIM + b] = carry;
            v_next = vt;
        }
        __syncwarp();
    }
}

extern "C" void kernel_launch(void* const* d_in, const int* in_sizes, int n_in,
                              void* d_out, int out_size)
{
    const float* value  = (const float*)d_in[0];
    const float* reward = (const float*)d_in[1];
    float* adv = (float*)d_out;

    dim3 grid(B_DIM / NCOL, 2);   // (512, 2): columns x time-chunk
    gae_kernel<<<grid, NCOL>>>(value, reward, adv);
}

// round 7
// speedup vs baseline: 1.0548x; 1.0548x over previous
#include <cuda_runtime.h>
#include <cstdint>

// GAE reverse scan: 2-way truncated-halo split + cp.async SMEM pipeline.
// R5 (NCOL=64, DEPTH=5) = best @ 75% DRAM; R6 (NCOL=32) regressed -> finer
// blocks don't help; plateau is the mixed read/write HBM ceiling. This round:
// R5 config + DEPTH=6 (48KB static smem, 5 stages in flight) + halo 256->192
// (split at 416, both chunks scan 608 steps; issued traffic 235->227MB).
// coef^192 ~ 4.2e-4 elementwise; expected global rel_err ~4e-5 (gate 1e-3).

#define T_DIM    1024
#define B_DIM    16384
#define GAMMA    0.99f
#define COEF     (0.99f * 0.97f)
#define UNR      16          // time rows per stage
#define NCOL     64          // columns per block (= blockDim.x, two warps)
#define DEPTH    6           // ring stages (48KB static smem total)
#define NSTAGES  38          // 608 / UNR (both chunks)
#define M_SPLIT  416         // bottom writes [0,416); top writes [416,1024)
#define B_HI     608         // bottom scan top = M_SPLIT + 192 halo

__device__ __forceinline__ uint32_t smem_u32(const void* p) {
    return (uint32_t)__cvta_generic_to_shared(p);
}

// Fill stage k_: UNR x NCOL tile of v and r via 16B cp.async.
// Tile = 1024 floats per array; per thread 4 float4 per array.
#define FILL_STAGE(k_)                                                        \
    {                                                                         \
        const int ts_   = t_hi - UNR * ((k_) + 1);                            \
        const int slot_ = (k_) % DEPTH;                                       \
        const uint32_t svb = smem_u32(&sv[slot_][0]);                         \
        const uint32_t srb = smem_u32(&sr[slot_][0]);                         \
        _Pragma("unroll")                                                     \
        for (int j = 0; j < 4; j++) {                                         \
            const int flat = j * 256 + tid * 4;   /* float index in tile */   \
            const size_t g = (size_t)(ts_ + (flat >> 6)) * B_DIM              \
                           + cb + (flat & 63);                                \
            asm volatile("cp.async.cg.shared.global [%0], [%1], 16;"          \
                         :: "r"(svb + flat * 4), "l"(value + g));             \
            asm volatile("cp.async.cg.shared.global [%0], [%1], 16;"          \
                         :: "r"(srb + flat * 4), "l"(reward + g));            \
        }                                                                     \
    }

__global__ void __launch_bounds__(NCOL) gae_kernel(
    const float* __restrict__ value,   // (T+1, B)
    const float* __restrict__ reward,  // (T, B)
    float* __restrict__ adv)           // (T, B)
{
    __shared__ float sv[DEPTH][UNR * NCOL];   // 24KB
    __shared__ float sr[DEPTH][UNR * NCOL];   // 24KB

    const int tid = threadIdx.x;
    const int cb  = blockIdx.x * NCOL;
    const int b   = cb + tid;
    const bool top = (blockIdx.y != 0);

    const int t_hi = top ? T_DIM : B_HI;       // 1024 : 608 (scan top, exclusive)
    const int wlim = top ? T_DIM : M_SPLIT;    // write rows with t < wlim

    float carry  = 0.0f;                       // exact (top) / truncated ~4e-4 elem
    float v_next = value[(size_t)t_hi * B_DIM + b];

    // Prologue: DEPTH-1 stages in flight before any compute.
    #pragma unroll
    for (int s = 0; s < DEPTH - 1; s++) {
        FILL_STAGE(s);
        asm volatile("cp.async.commit_group;");
    }

    for (int k = 0; k < NSTAGES; k++) {
        // Stage k complete when <= DEPTH-2 groups pending.
        asm volatile("cp.async.wait_group %0;" :: "n"(DEPTH - 2));
        __syncthreads();   // all threads' copies visible to all

        // Refill the slot freed by stage k-1 (its readers finished pre-barrier).
        if (k + DEPTH - 1 < NSTAGES) {
            FILL_STAGE(k + DEPTH - 1);
        }
        asm volatile("cp.async.commit_group;");   // empty tail groups keep counts aligned

        // Consume stage k: time descending within the stage.
        const int  slot     = k % DEPTH;
        const int  ts       = t_hi - UNR * (k + 1);
        const bool do_write = (ts + UNR <= wlim);
        #pragma unroll
        for (int j = UNR - 1; j >= 0; j--) {
            const float vt = sv[slot][j * NCOL + tid];
            const float rt = sr[slot][j * NCOL + tid];
            const float delta = fmaf(GAMMA, v_next, rt) - vt;
            carry = fmaf(COEF, carry, delta);
            if (do_write)
                adv[(size_t)(ts + j) * B_DIM + b] = carry;
            v_next = vt;
        }
    }
}

extern "C" void kernel_launch(void* const* d_in, const int* in_sizes, int n_in,
                              void* d_out, int out_size)
{
    const float* value  = (const float*)d_in[0];
    const float* reward = (const float*)d_in[1];
    float* adv = (float*)d_out;

    dim3 grid(B_DIM / NCOL, 2);   // (256, 2): columns x time-chunk
    gae_kernel<<<grid, NCOL>>>(value, reward, adv);
}

// round 8
// speedup vs baseline: 1.1070x; 1.0495x over previous
#include <cuda_runtime.h>
#include <cstdint>

// GAE reverse scan: 2-way truncated-halo split + cp.async SMEM pipeline.
// Config = R5's best-BW pipeline (NCOL=64, DEPTH=5 -> 40KB smem, 5 blocks/SM)
//        + R7's lowest-traffic geometry (halo 192, split at 416, 38 stages)
//        + streaming stores (st.global.cs) so the zero-reuse adv write stream
//          doesn't evict the halo overlap from L2.
// coef^192 ~ 4.2e-4 elementwise; measured global rel_err ~4.6e-5 (gate 1e-3).

#define T_DIM    1024
#define B_DIM    16384
#define GAMMA    0.99f
#define COEF     (0.99f * 0.97f)
#define UNR      16          // time rows per stage
#define NCOL     64          // columns per block (= blockDim.x, two warps)
#define DEPTH    5           // ring stages (40KB static smem -> 5 blocks/SM)
#define NSTAGES  38          // 608 / UNR (both chunks)
#define M_SPLIT  416         // bottom writes [0,416); top writes [416,1024)
#define B_HI     608         // bottom scan top = M_SPLIT + 192 halo

__device__ __forceinline__ uint32_t smem_u32(const void* p) {
    return (uint32_t)__cvta_generic_to_shared(p);
}

// Fill stage k_: UNR x NCOL tile of v and r via 16B cp.async (L2-cached .cg).
#define FILL_STAGE(k_)                                                        \
    {                                                                         \
        const int ts_   = t_hi - UNR * ((k_) + 1);                            \
        const int slot_ = (k_) % DEPTH;                                       \
        const uint32_t svb = smem_u32(&sv[slot_][0]);                         \
        const uint32_t srb = smem_u32(&sr[slot_][0]);                         \
        _Pragma("unroll")                                                     \
        for (int j = 0; j < 4; j++) {                                         \
            const int flat = j * 256 + tid * 4;   /* float index in tile */   \
            const size_t g = (size_t)(ts_ + (flat >> 6)) * B_DIM              \
                           + cb + (flat & 63);                                \
            asm volatile("cp.async.cg.shared.global [%0], [%1], 16;"          \
                         :: "r"(svb + flat * 4), "l"(value + g));             \
            asm volatile("cp.async.cg.shared.global [%0], [%1], 16;"          \
                         :: "r"(srb + flat * 4), "l"(reward + g));            \
        }                                                                     \
    }

__global__ void __launch_bounds__(NCOL) gae_kernel(
    const float* __restrict__ value,   // (T+1, B)
    const float* __restrict__ reward,  // (T, B)
    float* __restrict__ adv)           // (T, B)
{
    __shared__ float sv[DEPTH][UNR * NCOL];   // 20KB
    __shared__ float sr[DEPTH][UNR * NCOL];   // 20KB

    const int tid = threadIdx.x;
    const int cb  = blockIdx.x * NCOL;
    const int b   = cb + tid;
    const bool top = (blockIdx.y != 0);

    const int t_hi = top ? T_DIM : B_HI;       // 1024 : 608 (scan top, exclusive)
    const int wlim = top ? T_DIM : M_SPLIT;    // write rows with t < wlim

    float carry  = 0.0f;                       // exact (top) / truncated bottom
    float v_next = value[(size_t)t_hi * B_DIM + b];

    // Prologue: DEPTH-1 stages in flight before any compute.
    #pragma unroll
    for (int s = 0; s < DEPTH - 1; s++) {
        FILL_STAGE(s);
        asm volatile("cp.async.commit_group;");
    }

    for (int k = 0; k < NSTAGES; k++) {
        // Stage k complete when <= DEPTH-2 groups pending.
        asm volatile("cp.async.wait_group %0;" :: "n"(DEPTH - 2));
        __syncthreads();   // all threads' copies visible to all

        // Refill the slot freed by stage k-1 (its readers finished pre-barrier).
        if (k + DEPTH - 1 < NSTAGES) {
            FILL_STAGE(k + DEPTH - 1);
        }
        asm volatile("cp.async.commit_group;");   // empty tail groups keep counts aligned

        // Consume stage k: time descending within the stage.
        const int  slot     = k % DEPTH;
        const int  ts       = t_hi - UNR * (k + 1);
        const bool do_write = (ts + UNR <= wlim);
        #pragma unroll
        for (int j = UNR - 1; j >= 0; j--) {
            const float vt = sv[slot][j * NCOL + tid];
            const float rt = sr[slot][j * NCOL + tid];
            const float delta = fmaf(GAMMA, v_next, rt) - vt;
            carry = fmaf(COEF, carry, delta);
            if (do_write)
                __stcs(&adv[(size_t)(ts + j) * B_DIM + b], carry);  // streaming: no L2 reuse
            v_next = vt;
        }
    }
}

extern "C" void kernel_launch(void* const* d_in, const int* in_sizes, int n_in,
                              void* d_out, int out_size)
{
    const float* value  = (const float*)d_in[0];
    const float* reward = (const float*)d_in[1];
    float* adv = (float*)d_out;

    dim3 grid(B_DIM / NCOL, 2);   // (256, 2): columns x time-chunk
    gae_kernel<<<grid, NCOL>>>(value, reward, adv);
}